// round 13
// baseline (speedup 1.0000x reference)
#include <cuda_runtime.h>
#include <cuda_fp16.h>
#include <math_constants.h>
#include <cstdint>

#define B_  8
#define S_  2048
#define D_  512
#define H_  8
#define DH_ 64
#define M_  (B_*S_)   // 16384
#define NT_ (S_/64)   // 32 key tiles
#define QT_ 128       // q-rows per attention CTA

// Scratch (allocation-free rule: __device__ globals) — all fp16
__device__ __half g_Q[B_*H_*S_*DH_];
__device__ __half g_K[B_*H_*S_*DH_];
__device__ __half g_V[B_*H_*S_*DH_];
__device__ __half g_O[M_*D_];
__device__ __half g_X[M_*D_];
__device__ __half g_Wi[3*D_*D_];
__device__ __half g_Wo[D_*D_];

// ---------------------------------------------------------------------------
// helpers
// ---------------------------------------------------------------------------
__device__ __forceinline__ unsigned h2u(float a, float b) {
    __half2 h = __floats2half2_rn(a, b);
    return *reinterpret_cast<unsigned*>(&h);
}
__device__ __forceinline__ float ex2f(float x) {
    float y;
    asm("ex2.approx.f32 %0, %1;" : "=f"(y) : "f"(x));
    return y;
}

// m16n8k16 fp16 mma, fp32 accumulate
__device__ __forceinline__ void mma16(float* c, const unsigned* a, const unsigned* b) {
    asm volatile(
        "mma.sync.aligned.m16n8k16.row.col.f32.f16.f16.f32 "
        "{%0,%1,%2,%3}, {%4,%5,%6,%7}, {%8,%9}, {%0,%1,%2,%3};"
        : "+f"(c[0]), "+f"(c[1]), "+f"(c[2]), "+f"(c[3])
        : "r"(a[0]), "r"(a[1]), "r"(a[2]), "r"(a[3]), "r"(b[0]), "r"(b[1]));
}

__device__ __forceinline__ void ldsm4(unsigned* r, unsigned addr) {
    asm volatile("ldmatrix.sync.aligned.m8n8.x4.shared.b16 {%0,%1,%2,%3}, [%4];"
                 : "=r"(r[0]), "=r"(r[1]), "=r"(r[2]), "=r"(r[3]) : "r"(addr));
}
__device__ __forceinline__ void ldsm4t(unsigned* r, unsigned addr) {
    asm volatile("ldmatrix.sync.aligned.m8n8.x4.trans.shared.b16 {%0,%1,%2,%3}, [%4];"
                 : "=r"(r[0]), "=r"(r[1]), "=r"(r[2]), "=r"(r[3]) : "r"(addr));
}

__device__ __forceinline__ unsigned sptr(const void* p) {
    return (unsigned)__cvta_generic_to_shared(p);
}
#define CP16(d, s)  asm volatile("cp.async.cg.shared.global [%0], [%1], 16;\n" :: "r"(d), "l"(s))
#define CPCOMMIT    asm volatile("cp.async.commit_group;\n")
#define CPWAIT1     asm volatile("cp.async.wait_group 1;\n")
#define CPWAIT0     asm volatile("cp.async.wait_group 0;\n")

// ---------------------------------------------------------------------------
// fp16 pre-round: all three tensors in one launch (fp32 -> fp16)
// ---------------------------------------------------------------------------
#define XN4  (M_*D_/4)
#define WIN4 (3*D_*D_/4)
#define WON4 (D_*D_/4)

__global__ void round_kernel(const float4* __restrict__ x,
                             const float4* __restrict__ wi,
                             const float4* __restrict__ wo,
                             uint2* __restrict__ gx,
                             uint2* __restrict__ gwi,
                             uint2* __restrict__ gwo) {
    int i = blockIdx.x * 256 + threadIdx.x;
    const float4* src; uint2* dst; int j;
    if (i < XN4)               { src = x;  dst = gx;  j = i; }
    else if (i < XN4 + WIN4)   { src = wi; dst = gwi; j = i - XN4; }
    else if (i < XN4+WIN4+WON4){ src = wo; dst = gwo; j = i - XN4 - WIN4; }
    else return;
    float4 v = src[j];
    dst[j] = make_uint2(h2u(v.x, v.y), h2u(v.z, v.w));
}

// ---------------------------------------------------------------------------
// fp16 GEMM: 128x128 CTA tile, 256 threads (8 warps 4x2), k-chunk 64 halves
// (=128B rows, pitch 144B), THREE-stage cp.async, ONE barrier per chunk.
// ---------------------------------------------------------------------------
#define PB  144          // byte pitch (72 halves)
#define STG (128*PB)     // 18432 B per stage tile

#define GISSUE(Xp, Wp, kc, stg) do {                                          \
        const __half* xs = (Xp) + (size_t)(m0 + lr) * D_ + (kc) + seg * 32;   \
        const __half* ws = (Wp) + (size_t)(n0 + lr) * D_ + (kc) + seg * 32;   \
        unsigned da = sptr(As + (stg)*STG + lr*PB + seg*64);                  \
        unsigned db = sptr(Bs + (stg)*STG + lr*PB + seg*64);                  \
        _Pragma("unroll")                                                     \
        for (int u = 0; u < 4; u++) {                                         \
            CP16(da + u*16, xs + u*8);                                        \
            CP16(db + u*16, ws + u*8);                                        \
        }                                                                     \
        CPCOMMIT;                                                             \
    } while (0)

// 3-stage, single-barrier mainloop. At iter c: chunks c (landed, via wait 1)
// and c+1 in flight; the bar (all warps done with compute c-1) frees buffer
// (c-1)%3 == (c+2)%3 for the chunk c+2 issue.
#define GEMM_BODY(Xp, Wp)                                                     \
    unsigned aA[2], aB[4];                                                    \
    _Pragma("unroll")                                                         \
    for (int mt = 0; mt < 2; mt++)                                            \
        aA[mt] = sptr(As) + (wm*32 + mt*16 + l8 + b3*8)*PB + b4*16;           \
    _Pragma("unroll")                                                         \
    for (int p = 0; p < 4; p++)                                               \
        aB[p] = sptr(Bs) + (wn*64 + p*16 + l8 + b4*8)*PB + b3*16;             \
    GISSUE(Xp, Wp, 0, 0);                                                     \
    GISSUE(Xp, Wp, 64, 1);                                                    \
    float acc[2][8][4];                                                       \
    _Pragma("unroll")                                                         \
    for (int mt = 0; mt < 2; mt++)                                            \
        _Pragma("unroll")                                                     \
        for (int nt = 0; nt < 8; nt++)                                        \
            _Pragma("unroll")                                                 \
            for (int i2 = 0; i2 < 4; i2++) acc[mt][nt][i2] = 0.f;             \
    for (int c = 0; c < 8; c++) {                                             \
        int stg = c % 3;                                                      \
        if (c + 1 < 8) { CPWAIT1; } else { CPWAIT0; }                         \
        __syncthreads();                                                      \
        if (c + 2 < 8) GISSUE(Xp, Wp, (c+2)*64, (c+2) % 3);                   \
        _Pragma("unroll")                                                     \
        for (int ks = 0; ks < 4; ks++) {                                      \
            unsigned off = (unsigned)stg*STG + ks*32;                         \
            unsigned a0[4], a1[4];                                            \
            ldsm4(a0, aA[0] + off);                                           \
            ldsm4(a1, aA[1] + off);                                           \
            _Pragma("unroll")                                                 \
            for (int p = 0; p < 4; p++) {                                     \
                unsigned bb[4];                                               \
                ldsm4(bb, aB[p] + off);                                       \
                mma16(acc[0][2*p],   a0, bb);                                 \
                mma16(acc[1][2*p],   a1, bb);                                 \
                mma16(acc[0][2*p+1], a0, bb + 2);                             \
                mma16(acc[1][2*p+1], a1, bb + 2);                             \
            }                                                                 \
        }                                                                     \
    }

// ---------------------------------------------------------------------------
// QKV projection: -> Q,K,V fp16 [B,H,S,Dh]; Q * 0.125*log2(e)
// ---------------------------------------------------------------------------
__global__ __launch_bounds__(256, 2) void qkv_kernel(const float* __restrict__ bias) {
    extern __shared__ char smc[];
    char* As = smc;
    char* Bs = smc + 3*STG;

    int tid = threadIdx.x;
    int m0 = blockIdx.y * 128, n0 = blockIdx.x * 128;
    int w = tid >> 5, lane = tid & 31;
    int wm = w >> 1, wn = w & 1;
    int g = lane >> 2, tg = lane & 3;
    int lr = tid >> 1, seg = tid & 1;
    int l8 = lane & 7, b3 = (lane >> 3) & 1, b4 = lane >> 4;

    GEMM_BODY(g_X, g_Wi)

    int sec = n0 >> 9;
    __half* dst = (sec == 0) ? g_Q : (sec == 1 ? g_K : g_V);
    float qs = (sec == 0) ? 0.125f * 1.4426950408889634f : 1.0f;
#pragma unroll
    for (int mt = 0; mt < 2; mt++) {
#pragma unroll
        for (int hf = 0; hf < 2; hf++) {
            int mm = m0 + wm * 32 + mt * 16 + g + hf * 8;
            int bb = mm >> 11, ss = mm & (S_ - 1);
#pragma unroll
            for (int nt = 0; nt < 8; nt++) {
                int col = n0 + wn * 64 + nt * 8 + 2 * tg;
                float2 bi = *(const float2*)(bias + col);
                float v0 = (acc[mt][nt][hf * 2 + 0] + bi.x) * qs;
                float v1 = (acc[mt][nt][hf * 2 + 1] + bi.y) * qs;
                int d = col & (D_ - 1);
                int hh = d >> 6, dh = d & 63;
                __half* p = dst + (((size_t)(bb * H_ + hh)) * S_ + ss) * DH_ + dh;
                *(unsigned*)p = h2u(v0, v1);
            }
        }
    }
}

// ---------------------------------------------------------------------------
// Output projection: out(fp32) = g_O(fp16) @ g_Wo^T + b_out
// ---------------------------------------------------------------------------
__global__ __launch_bounds__(256, 2) void out_kernel(const float* __restrict__ bias,
                                                     float* __restrict__ out) {
    extern __shared__ char smc[];
    char* As = smc;
    char* Bs = smc + 3*STG;

    int tid = threadIdx.x;
    int m0 = blockIdx.y * 128, n0 = blockIdx.x * 128;
    int w = tid >> 5, lane = tid & 31;
    int wm = w >> 1, wn = w & 1;
    int g = lane >> 2, tg = lane & 3;
    int lr = tid >> 1, seg = tid & 1;
    int l8 = lane & 7, b3 = (lane >> 3) & 1, b4 = lane >> 4;

    GEMM_BODY(g_O, g_Wo)

#pragma unroll
    for (int mt = 0; mt < 2; mt++) {
#pragma unroll
        for (int hf = 0; hf < 2; hf++) {
            int mm = m0 + wm * 32 + mt * 16 + g + hf * 8;
#pragma unroll
            for (int nt = 0; nt < 8; nt++) {
                int col = n0 + wn * 64 + nt * 8 + 2 * tg;
                float2 bi = *(const float2*)(bias + col);
                *(float2*)&out[(size_t)mm * D_ + col] =
                    make_float2(acc[mt][nt][hf * 2 + 0] + bi.x,
                                acc[mt][nt][hf * 2 + 1] + bi.y);
            }
        }
    }
}

// ---------------------------------------------------------------------------
// Flash attention, fp16 mma. Double-buffered K/V, ONE bar per tile.
// P stays entirely in registers (S-accum layout == PV A-frag layout).
// 3 CTAs/SM for latency interleaving of the S->softmax->PV chain.
// ---------------------------------------------------------------------------
#define AP  144            // byte pitch
#define KTB (64*AP)        // 9216 B per K or V buffer

__global__ __launch_bounds__(128, 3) void attn_kernel() {
    extern __shared__ char smc[];
    char* SP = smc;                   // 128 rows: Q (prologue only)
    char* KB = smc + 128*AP;          // 2 x 64 rows
    char* VB = KB + 2*KTB;            // 2 x 64 rows

    int qt = blockIdx.x, h = blockIdx.y, b = blockIdx.z;
    const __half* Qg = g_Q + (((size_t)(b * H_ + h)) * S_ + qt * QT_) * DH_;
    const __half* Kg = g_K + ((size_t)(b * H_ + h)) * S_ * DH_;
    const __half* Vg = g_V + ((size_t)(b * H_ + h)) * S_ * DH_;

    int tid = threadIdx.x, w = tid >> 5, lane = tid & 31;
    int g = lane >> 2, tg = lane & 3;
    int l8 = lane & 7, b3 = (lane >> 3) & 1, b4 = lane >> 4;
    int r0 = w * 32;

    unsigned aSP[2], aK[4], aV[4];
#pragma unroll
    for (int f = 0; f < 2; f++)
        aSP[f] = sptr(SP) + (r0 + f*16 + l8 + b3*8)*AP + b4*16;
#pragma unroll
    for (int p = 0; p < 4; p++) {
        aK[p] = sptr(KB) + (p*16 + l8 + b4*8)*AP + b3*16;
        aV[p] = sptr(VB) + (l8 + b3*8)*AP + p*32 + b4*16;
    }

    // prologue: Q -> SP ; K0+V0 -> buffers 0
#pragma unroll
    for (int p = 0; p < 8; p++) {
        int slot = tid + p * 128, row = slot >> 3, u = slot & 7;
        CP16(sptr(SP + row*AP + u*16), Qg + row * DH_ + u * 8);
    }
    CPCOMMIT;
#pragma unroll
    for (int p = 0; p < 4; p++) {
        int slot = tid + p * 128, row = slot >> 3, u = slot & 7;
        CP16(sptr(KB + row*AP + u*16), Kg + row * DH_ + u * 8);
        CP16(sptr(VB + row*AP + u*16), Vg + row * DH_ + u * 8);
    }
    CPCOMMIT;
    CPWAIT1;
    __syncthreads();

    unsigned qf[2][4][4];
#pragma unroll
    for (int f = 0; f < 2; f++)
#pragma unroll
        for (int ks = 0; ks < 4; ks++)
            ldsm4(qf[f][ks], aSP[f] + ks * 32);

    float oacc[2][8][4];
#pragma unroll
    for (int f = 0; f < 2; f++)
#pragma unroll
        for (int dt = 0; dt < 8; dt++)
#pragma unroll
            for (int i = 0; i < 4; i++) oacc[f][dt][i] = 0.f;
    float mrow[2][2], lrow[2][2];
#pragma unroll
    for (int f = 0; f < 2; f++) {
        mrow[f][0] = -CUDART_INF_F; mrow[f][1] = -CUDART_INF_F;
        lrow[f][0] = 0.f; lrow[f][1] = 0.f;
    }

    for (int kt = 0; kt < NT_; kt++) {
        int cur = kt & 1, nxt = cur ^ 1;
        CPWAIT0;
        __syncthreads();

        // prefetch (K,V)[kt+1]
        {
            int t1 = (kt + 1) & (NT_ - 1);
            const __half* Kt = Kg + (size_t)t1 * 64 * DH_;
            const __half* Vt = Vg + (size_t)t1 * 64 * DH_;
#pragma unroll
            for (int p = 0; p < 4; p++) {
                int slot = tid + p * 128, row = slot >> 3, u = slot & 7;
                CP16(sptr(KB + nxt*KTB + row*AP + u*16), Kt + row * DH_ + u * 8);
                CP16(sptr(VB + nxt*KTB + row*AP + u*16), Vt + row * DH_ + u * 8);
            }
            CPCOMMIT;
        }

        // S = Q K^T
        float s[2][8][4];
#pragma unroll
        for (int f = 0; f < 2; f++)
#pragma unroll
            for (int nt = 0; nt < 8; nt++)
#pragma unroll
                for (int i = 0; i < 4; i++) s[f][nt][i] = 0.f;
#pragma unroll
        for (int ks = 0; ks < 4; ks++) {
            unsigned off = (unsigned)cur*KTB + ks*32;
#pragma unroll
            for (int p = 0; p < 4; p++) {
                unsigned bb[4];
                ldsm4(bb, aK[p] + off);
                mma16(s[0][2*p],   qf[0][ks], bb);
                mma16(s[1][2*p],   qf[1][ks], bb);
                mma16(s[0][2*p+1], qf[0][ks], bb + 2);
                mma16(s[1][2*p+1], qf[1][ks], bb + 2);
            }
        }

        // online softmax (exp2 domain) — P stays in registers
#pragma unroll
        for (int f = 0; f < 2; f++) {
            float mxl = -CUDART_INF_F, mxh = -CUDART_INF_F;
#pragma unroll
            for (int nt = 0; nt < 8; nt++) {
                mxl = fmaxf(mxl, fmaxf(s[f][nt][0], s[f][nt][1]));
                mxh = fmaxf(mxh, fmaxf(s[f][nt][2], s[f][nt][3]));
            }
            mxl = fmaxf(mxl, __shfl_xor_sync(0xffffffffu, mxl, 1));
            mxl = fmaxf(mxl, __shfl_xor_sync(0xffffffffu, mxl, 2));
            mxh = fmaxf(mxh, __shfl_xor_sync(0xffffffffu, mxh, 1));
            mxh = fmaxf(mxh, __shfl_xor_sync(0xffffffffu, mxh, 2));
            float mnl = fmaxf(mrow[f][0], mxl), mnh = fmaxf(mrow[f][1], mxh);
            float al = ex2f(mrow[f][0] - mnl), ah = ex2f(mrow[f][1] - mnh);
            mrow[f][0] = mnl; mrow[f][1] = mnh;
            float rsl = 0.f, rsh = 0.f;
#pragma unroll
            for (int nt = 0; nt < 8; nt++) {
                s[f][nt][0] = ex2f(s[f][nt][0] - mnl);
                s[f][nt][1] = ex2f(s[f][nt][1] - mnl);
                s[f][nt][2] = ex2f(s[f][nt][2] - mnh);
                s[f][nt][3] = ex2f(s[f][nt][3] - mnh);
                rsl += s[f][nt][0] + s[f][nt][1];
                rsh += s[f][nt][2] + s[f][nt][3];
            }
            rsl += __shfl_xor_sync(0xffffffffu, rsl, 1);
            rsl += __shfl_xor_sync(0xffffffffu, rsl, 2);
            rsh += __shfl_xor_sync(0xffffffffu, rsh, 1);
            rsh += __shfl_xor_sync(0xffffffffu, rsh, 2);
            lrow[f][0] = lrow[f][0] * al + rsl;
            lrow[f][1] = lrow[f][1] * ah + rsh;
#pragma unroll
            for (int dt = 0; dt < 8; dt++) {
                oacc[f][dt][0] *= al; oacc[f][dt][1] *= al;
                oacc[f][dt][2] *= ah; oacc[f][dt][3] *= ah;
            }
        }

        // O += P V : P A-frags in-register; V B-frags via ldmatrix.trans
#pragma unroll
        for (int ks = 0; ks < 4; ks++) {
            unsigned pa[2][4];
#pragma unroll
            for (int f = 0; f < 2; f++) {
                pa[f][0] = h2u(s[f][2*ks][0],   s[f][2*ks][1]);
                pa[f][1] = h2u(s[f][2*ks][2],   s[f][2*ks][3]);
                pa[f][2] = h2u(s[f][2*ks+1][0], s[f][2*ks+1][1]);
                pa[f][3] = h2u(s[f][2*ks+1][2], s[f][2*ks+1][3]);
            }
            unsigned voff = (unsigned)cur*KTB + ks*16*AP;
#pragma unroll
            for (int p = 0; p < 4; p++) {
                unsigned vb[4];
                ldsm4t(vb, aV[p] + voff);
                mma16(oacc[0][2*p],   pa[0], vb);
                mma16(oacc[1][2*p],   pa[1], vb);
                mma16(oacc[0][2*p+1], pa[0], vb + 2);
                mma16(oacc[1][2*p+1], pa[1], vb + 2);
            }
        }
    }

    // epilogue
    __half* Og = g_O + ((size_t)(b * S_ + qt * QT_)) * D_ + h * DH_;
#pragma unroll
    for (int f = 0; f < 2; f++) {
        float il = 1.0f / lrow[f][0], ih = 1.0f / lrow[f][1];
        int rl = r0 + f * 16 + g, rh = rl + 8;
#pragma unroll
        for (int dt = 0; dt < 8; dt++) {
            int c = dt * 8 + 2 * tg;
            *(unsigned*)&Og[(size_t)rl * D_ + c] = h2u(oacc[f][dt][0] * il, oacc[f][dt][1] * il);
            *(unsigned*)&Og[(size_t)rh * D_ + c] = h2u(oacc[f][dt][2] * ih, oacc[f][dt][3] * ih);
        }
    }
}

// ---------------------------------------------------------------------------
extern "C" void kernel_launch(void* const* d_in, const int* in_sizes, int n_in,
                              void* d_out, int out_size) {
    const float* x     = (const float*)d_in[0];
    const float* w_in  = (const float*)d_in[1];
    const float* b_in  = (const float*)d_in[2];
    const float* w_out = (const float*)d_in[3];
    const float* b_out = (const float*)d_in[4];
    float* out = (float*)d_out;

    const int gemm_smem = 6 * STG;                    // 110592 B
    const int attn_smem = 128*AP + 4*KTB;             // 55296 B
    cudaFuncSetAttribute(qkv_kernel,  cudaFuncAttributeMaxDynamicSharedMemorySize, gemm_smem);
    cudaFuncSetAttribute(out_kernel,  cudaFuncAttributeMaxDynamicSharedMemorySize, gemm_smem);
    cudaFuncSetAttribute(attn_kernel, cudaFuncAttributeMaxDynamicSharedMemorySize, attn_smem);

    __half* gx;  cudaGetSymbolAddress((void**)&gx,  g_X);
    __half* gwi; cudaGetSymbolAddress((void**)&gwi, g_Wi);
    __half* gwo; cudaGetSymbolAddress((void**)&gwo, g_Wo);
    int tot4 = XN4 + WIN4 + WON4;
    round_kernel<<<(tot4 + 255) / 256, 256>>>(
        (const float4*)x, (const float4*)w_in, (const float4*)w_out,
        (uint2*)gx, (uint2*)gwi, (uint2*)gwo);

    qkv_kernel<<<dim3(12, 128), 256, gemm_smem>>>(b_in);
    attn_kernel<<<dim3(S_ / QT_, H_, B_), 128, attn_smem>>>();
    out_kernel<<<dim3(4, 128), 256, gemm_smem>>>(b_out, out);
}

// round 14
// speedup vs baseline: 1.1171x; 1.1171x over previous
#include <cuda_runtime.h>
#include <cuda_fp16.h>
#include <math_constants.h>
#include <cstdint>

#define B_  8
#define S_  2048
#define D_  512
#define H_  8
#define DH_ 64
#define M_  (B_*S_)   // 16384
#define NT_ (S_/64)   // 32 key tiles
#define QT_ 128       // q-rows per attention CTA

// Scratch (allocation-free rule: __device__ globals) — all fp16
__device__ __half g_Q[B_*H_*S_*DH_];
__device__ __half g_K[B_*H_*S_*DH_];
__device__ __half g_V[B_*H_*S_*DH_];
__device__ __half g_O[M_*D_];
__device__ __half g_X[M_*D_];
__device__ __half g_Wi[3*D_*D_];
__device__ __half g_Wo[D_*D_];

// ---------------------------------------------------------------------------
// helpers
// ---------------------------------------------------------------------------
__device__ __forceinline__ unsigned h2u(float a, float b) {
    __half2 h = __floats2half2_rn(a, b);
    return *reinterpret_cast<unsigned*>(&h);
}
__device__ __forceinline__ float ex2f(float x) {
    float y;
    asm("ex2.approx.f32 %0, %1;" : "=f"(y) : "f"(x));
    return y;
}

// m16n8k16 fp16 mma, fp32 accumulate
__device__ __forceinline__ void mma16(float* c, const unsigned* a, const unsigned* b) {
    asm volatile(
        "mma.sync.aligned.m16n8k16.row.col.f32.f16.f16.f32 "
        "{%0,%1,%2,%3}, {%4,%5,%6,%7}, {%8,%9}, {%0,%1,%2,%3};"
        : "+f"(c[0]), "+f"(c[1]), "+f"(c[2]), "+f"(c[3])
        : "r"(a[0]), "r"(a[1]), "r"(a[2]), "r"(a[3]), "r"(b[0]), "r"(b[1]));
}

__device__ __forceinline__ void ldsm4(unsigned* r, unsigned addr) {
    asm volatile("ldmatrix.sync.aligned.m8n8.x4.shared.b16 {%0,%1,%2,%3}, [%4];"
                 : "=r"(r[0]), "=r"(r[1]), "=r"(r[2]), "=r"(r[3]) : "r"(addr));
}
__device__ __forceinline__ void ldsm4t(unsigned* r, unsigned addr) {
    asm volatile("ldmatrix.sync.aligned.m8n8.x4.trans.shared.b16 {%0,%1,%2,%3}, [%4];"
                 : "=r"(r[0]), "=r"(r[1]), "=r"(r[2]), "=r"(r[3]) : "r"(addr));
}

__device__ __forceinline__ unsigned sptr(const void* p) {
    return (unsigned)__cvta_generic_to_shared(p);
}
#define CP16(d, s)  asm volatile("cp.async.cg.shared.global [%0], [%1], 16;\n" :: "r"(d), "l"(s))
#define CPCOMMIT    asm volatile("cp.async.commit_group;\n")
#define CPWAIT1     asm volatile("cp.async.wait_group 1;\n")
#define CPWAIT0     asm volatile("cp.async.wait_group 0;\n")

// ---------------------------------------------------------------------------
// fp16 pre-round: all three tensors in one launch (fp32 -> fp16)
// ---------------------------------------------------------------------------
#define XN4  (M_*D_/4)
#define WIN4 (3*D_*D_/4)
#define WON4 (D_*D_/4)

__global__ void round_kernel(const float4* __restrict__ x,
                             const float4* __restrict__ wi,
                             const float4* __restrict__ wo,
                             uint2* __restrict__ gx,
                             uint2* __restrict__ gwi,
                             uint2* __restrict__ gwo) {
    int i = blockIdx.x * 256 + threadIdx.x;
    const float4* src; uint2* dst; int j;
    if (i < XN4)               { src = x;  dst = gx;  j = i; }
    else if (i < XN4 + WIN4)   { src = wi; dst = gwi; j = i - XN4; }
    else if (i < XN4+WIN4+WON4){ src = wo; dst = gwo; j = i - XN4 - WIN4; }
    else return;
    float4 v = src[j];
    dst[j] = make_uint2(h2u(v.x, v.y), h2u(v.z, v.w));
}

// ---------------------------------------------------------------------------
// fp16 GEMM: 128x128 CTA tile, 256 threads (8 warps 4x2), k-chunk 64 halves
// (=128B rows, pitch 144B), THREE-stage cp.async, ONE barrier per chunk.
// ---------------------------------------------------------------------------
#define PB  144          // byte pitch (72 halves)
#define STG (128*PB)     // 18432 B per stage tile

#define GISSUE(Xp, Wp, kc, stg) do {                                          \
        const __half* xs = (Xp) + (size_t)(m0 + lr) * D_ + (kc) + seg * 32;   \
        const __half* ws = (Wp) + (size_t)(n0 + lr) * D_ + (kc) + seg * 32;   \
        unsigned da = sptr(As + (stg)*STG + lr*PB + seg*64);                  \
        unsigned db = sptr(Bs + (stg)*STG + lr*PB + seg*64);                  \
        _Pragma("unroll")                                                     \
        for (int u = 0; u < 4; u++) {                                         \
            CP16(da + u*16, xs + u*8);                                        \
            CP16(db + u*16, ws + u*8);                                        \
        }                                                                     \
        CPCOMMIT;                                                             \
    } while (0)

// 3-stage, single-barrier mainloop. At iter c: chunks c (landed, via wait 1)
// and c+1 in flight; the bar (all warps done with compute c-1) frees buffer
// (c-1)%3 == (c+2)%3 for the chunk c+2 issue.
#define GEMM_BODY(Xp, Wp)                                                     \
    unsigned aA[2], aB[4];                                                    \
    _Pragma("unroll")                                                         \
    for (int mt = 0; mt < 2; mt++)                                            \
        aA[mt] = sptr(As) + (wm*32 + mt*16 + l8 + b3*8)*PB + b4*16;           \
    _Pragma("unroll")                                                         \
    for (int p = 0; p < 4; p++)                                               \
        aB[p] = sptr(Bs) + (wn*64 + p*16 + l8 + b4*8)*PB + b3*16;             \
    GISSUE(Xp, Wp, 0, 0);                                                     \
    GISSUE(Xp, Wp, 64, 1);                                                    \
    float acc[2][8][4];                                                       \
    _Pragma("unroll")                                                         \
    for (int mt = 0; mt < 2; mt++)                                            \
        _Pragma("unroll")                                                     \
        for (int nt = 0; nt < 8; nt++)                                        \
            _Pragma("unroll")                                                 \
            for (int i2 = 0; i2 < 4; i2++) acc[mt][nt][i2] = 0.f;             \
    for (int c = 0; c < 8; c++) {                                             \
        int stg = c % 3;                                                      \
        if (c + 1 < 8) { CPWAIT1; } else { CPWAIT0; }                         \
        __syncthreads();                                                      \
        if (c + 2 < 8) GISSUE(Xp, Wp, (c+2)*64, (c+2) % 3);                   \
        _Pragma("unroll")                                                     \
        for (int ks = 0; ks < 4; ks++) {                                      \
            unsigned off = (unsigned)stg*STG + ks*32;                         \
            unsigned a0[4], a1[4];                                            \
            ldsm4(a0, aA[0] + off);                                           \
            ldsm4(a1, aA[1] + off);                                           \
            _Pragma("unroll")                                                 \
            for (int p = 0; p < 4; p++) {                                     \
                unsigned bb[4];                                               \
                ldsm4(bb, aB[p] + off);                                       \
                mma16(acc[0][2*p],   a0, bb);                                 \
                mma16(acc[1][2*p],   a1, bb);                                 \
                mma16(acc[0][2*p+1], a0, bb + 2);                             \
                mma16(acc[1][2*p+1], a1, bb + 2);                             \
            }                                                                 \
        }                                                                     \
    }

// ---------------------------------------------------------------------------
// QKV projection: -> Q,K,V fp16 [B,H,S,Dh]; Q * 0.125*log2(e)
// ---------------------------------------------------------------------------
__global__ __launch_bounds__(256, 2) void qkv_kernel(const float* __restrict__ bias) {
    extern __shared__ char smc[];
    char* As = smc;
    char* Bs = smc + 3*STG;

    int tid = threadIdx.x;
    int m0 = blockIdx.y * 128, n0 = blockIdx.x * 128;
    int w = tid >> 5, lane = tid & 31;
    int wm = w >> 1, wn = w & 1;
    int g = lane >> 2, tg = lane & 3;
    int lr = tid >> 1, seg = tid & 1;
    int l8 = lane & 7, b3 = (lane >> 3) & 1, b4 = lane >> 4;

    GEMM_BODY(g_X, g_Wi)

    int sec = n0 >> 9;
    __half* dst = (sec == 0) ? g_Q : (sec == 1 ? g_K : g_V);
    float qs = (sec == 0) ? 0.125f * 1.4426950408889634f : 1.0f;
#pragma unroll
    for (int mt = 0; mt < 2; mt++) {
#pragma unroll
        for (int hf = 0; hf < 2; hf++) {
            int mm = m0 + wm * 32 + mt * 16 + g + hf * 8;
            int bb = mm >> 11, ss = mm & (S_ - 1);
#pragma unroll
            for (int nt = 0; nt < 8; nt++) {
                int col = n0 + wn * 64 + nt * 8 + 2 * tg;
                float2 bi = *(const float2*)(bias + col);
                float v0 = (acc[mt][nt][hf * 2 + 0] + bi.x) * qs;
                float v1 = (acc[mt][nt][hf * 2 + 1] + bi.y) * qs;
                int d = col & (D_ - 1);
                int hh = d >> 6, dh = d & 63;
                __half* p = dst + (((size_t)(bb * H_ + hh)) * S_ + ss) * DH_ + dh;
                *(unsigned*)p = h2u(v0, v1);
            }
        }
    }
}

// ---------------------------------------------------------------------------
// Output projection: out(fp32) = g_O(fp16) @ g_Wo^T + b_out
// ---------------------------------------------------------------------------
__global__ __launch_bounds__(256, 2) void out_kernel(const float* __restrict__ bias,
                                                     float* __restrict__ out) {
    extern __shared__ char smc[];
    char* As = smc;
    char* Bs = smc + 3*STG;

    int tid = threadIdx.x;
    int m0 = blockIdx.y * 128, n0 = blockIdx.x * 128;
    int w = tid >> 5, lane = tid & 31;
    int wm = w >> 1, wn = w & 1;
    int g = lane >> 2, tg = lane & 3;
    int lr = tid >> 1, seg = tid & 1;
    int l8 = lane & 7, b3 = (lane >> 3) & 1, b4 = lane >> 4;

    GEMM_BODY(g_O, g_Wo)

#pragma unroll
    for (int mt = 0; mt < 2; mt++) {
#pragma unroll
        for (int hf = 0; hf < 2; hf++) {
            int mm = m0 + wm * 32 + mt * 16 + g + hf * 8;
#pragma unroll
            for (int nt = 0; nt < 8; nt++) {
                int col = n0 + wn * 64 + nt * 8 + 2 * tg;
                float2 bi = *(const float2*)(bias + col);
                *(float2*)&out[(size_t)mm * D_ + col] =
                    make_float2(acc[mt][nt][hf * 2 + 0] + bi.x,
                                acc[mt][nt][hf * 2 + 1] + bi.y);
            }
        }
    }
}

// ---------------------------------------------------------------------------
// Flash attention, fp16 mma. Double-buffered K/V, ONE bar per tile.
// P stays entirely in registers (S-accum layout == PV A-frag layout).
// 2 CTAs/SM (3 spills registers — verified regression in round 13).
// ---------------------------------------------------------------------------
#define AP  144            // byte pitch
#define KTB (64*AP)        // 9216 B per K or V buffer

__global__ __launch_bounds__(128, 2) void attn_kernel() {
    extern __shared__ char smc[];
    char* SP = smc;                   // 128 rows: Q (prologue only)
    char* KB = smc + 128*AP;          // 2 x 64 rows
    char* VB = KB + 2*KTB;            // 2 x 64 rows

    int qt = blockIdx.x, h = blockIdx.y, b = blockIdx.z;
    const __half* Qg = g_Q + (((size_t)(b * H_ + h)) * S_ + qt * QT_) * DH_;
    const __half* Kg = g_K + ((size_t)(b * H_ + h)) * S_ * DH_;
    const __half* Vg = g_V + ((size_t)(b * H_ + h)) * S_ * DH_;

    int tid = threadIdx.x, w = tid >> 5, lane = tid & 31;
    int g = lane >> 2, tg = lane & 3;
    int l8 = lane & 7, b3 = (lane >> 3) & 1, b4 = lane >> 4;
    int r0 = w * 32;

    unsigned aSP[2], aK[4], aV[4];
#pragma unroll
    for (int f = 0; f < 2; f++)
        aSP[f] = sptr(SP) + (r0 + f*16 + l8 + b3*8)*AP + b4*16;
#pragma unroll
    for (int p = 0; p < 4; p++) {
        aK[p] = sptr(KB) + (p*16 + l8 + b4*8)*AP + b3*16;
        aV[p] = sptr(VB) + (l8 + b3*8)*AP + p*32 + b4*16;
    }

    // prologue: Q -> SP ; K0+V0 -> buffers 0
#pragma unroll
    for (int p = 0; p < 8; p++) {
        int slot = tid + p * 128, row = slot >> 3, u = slot & 7;
        CP16(sptr(SP + row*AP + u*16), Qg + row * DH_ + u * 8);
    }
    CPCOMMIT;
#pragma unroll
    for (int p = 0; p < 4; p++) {
        int slot = tid + p * 128, row = slot >> 3, u = slot & 7;
        CP16(sptr(KB + row*AP + u*16), Kg + row * DH_ + u * 8);
        CP16(sptr(VB + row*AP + u*16), Vg + row * DH_ + u * 8);
    }
    CPCOMMIT;
    CPWAIT1;
    __syncthreads();

    unsigned qf[2][4][4];
#pragma unroll
    for (int f = 0; f < 2; f++)
#pragma unroll
        for (int ks = 0; ks < 4; ks++)
            ldsm4(qf[f][ks], aSP[f] + ks * 32);

    float oacc[2][8][4];
#pragma unroll
    for (int f = 0; f < 2; f++)
#pragma unroll
        for (int dt = 0; dt < 8; dt++)
#pragma unroll
            for (int i = 0; i < 4; i++) oacc[f][dt][i] = 0.f;
    float mrow[2][2], lrow[2][2];
#pragma unroll
    for (int f = 0; f < 2; f++) {
        mrow[f][0] = -CUDART_INF_F; mrow[f][1] = -CUDART_INF_F;
        lrow[f][0] = 0.f; lrow[f][1] = 0.f;
    }

    for (int kt = 0; kt < NT_; kt++) {
        int cur = kt & 1, nxt = cur ^ 1;
        CPWAIT0;
        __syncthreads();

        // prefetch (K,V)[kt+1]
        {
            int t1 = (kt + 1) & (NT_ - 1);
            const __half* Kt = Kg + (size_t)t1 * 64 * DH_;
            const __half* Vt = Vg + (size_t)t1 * 64 * DH_;
#pragma unroll
            for (int p = 0; p < 4; p++) {
                int slot = tid + p * 128, row = slot >> 3, u = slot & 7;
                CP16(sptr(KB + nxt*KTB + row*AP + u*16), Kt + row * DH_ + u * 8);
                CP16(sptr(VB + nxt*KTB + row*AP + u*16), Vt + row * DH_ + u * 8);
            }
            CPCOMMIT;
        }

        // S = Q K^T
        float s[2][8][4];
#pragma unroll
        for (int f = 0; f < 2; f++)
#pragma unroll
            for (int nt = 0; nt < 8; nt++)
#pragma unroll
                for (int i = 0; i < 4; i++) s[f][nt][i] = 0.f;
#pragma unroll
        for (int ks = 0; ks < 4; ks++) {
            unsigned off = (unsigned)cur*KTB + ks*32;
#pragma unroll
            for (int p = 0; p < 4; p++) {
                unsigned bb[4];
                ldsm4(bb, aK[p] + off);
                mma16(s[0][2*p],   qf[0][ks], bb);
                mma16(s[1][2*p],   qf[1][ks], bb);
                mma16(s[0][2*p+1], qf[0][ks], bb + 2);
                mma16(s[1][2*p+1], qf[1][ks], bb + 2);
            }
        }

        // online softmax (exp2 domain) — P stays in registers
#pragma unroll
        for (int f = 0; f < 2; f++) {
            float mxl = -CUDART_INF_F, mxh = -CUDART_INF_F;
#pragma unroll
            for (int nt = 0; nt < 8; nt++) {
                mxl = fmaxf(mxl, fmaxf(s[f][nt][0], s[f][nt][1]));
                mxh = fmaxf(mxh, fmaxf(s[f][nt][2], s[f][nt][3]));
            }
            mxl = fmaxf(mxl, __shfl_xor_sync(0xffffffffu, mxl, 1));
            mxl = fmaxf(mxl, __shfl_xor_sync(0xffffffffu, mxl, 2));
            mxh = fmaxf(mxh, __shfl_xor_sync(0xffffffffu, mxh, 1));
            mxh = fmaxf(mxh, __shfl_xor_sync(0xffffffffu, mxh, 2));
            float mnl = fmaxf(mrow[f][0], mxl), mnh = fmaxf(mrow[f][1], mxh);
            float al = ex2f(mrow[f][0] - mnl), ah = ex2f(mrow[f][1] - mnh);
            mrow[f][0] = mnl; mrow[f][1] = mnh;
            float rsl = 0.f, rsh = 0.f;
#pragma unroll
            for (int nt = 0; nt < 8; nt++) {
                s[f][nt][0] = ex2f(s[f][nt][0] - mnl);
                s[f][nt][1] = ex2f(s[f][nt][1] - mnl);
                s[f][nt][2] = ex2f(s[f][nt][2] - mnh);
                s[f][nt][3] = ex2f(s[f][nt][3] - mnh);
                rsl += s[f][nt][0] + s[f][nt][1];
                rsh += s[f][nt][2] + s[f][nt][3];
            }
            rsl += __shfl_xor_sync(0xffffffffu, rsl, 1);
            rsl += __shfl_xor_sync(0xffffffffu, rsl, 2);
            rsh += __shfl_xor_sync(0xffffffffu, rsh, 1);
            rsh += __shfl_xor_sync(0xffffffffu, rsh, 2);
            lrow[f][0] = lrow[f][0] * al + rsl;
            lrow[f][1] = lrow[f][1] * ah + rsh;
#pragma unroll
            for (int dt = 0; dt < 8; dt++) {
                oacc[f][dt][0] *= al; oacc[f][dt][1] *= al;
                oacc[f][dt][2] *= ah; oacc[f][dt][3] *= ah;
            }
        }

        // O += P V : P A-frags in-register; V B-frags via ldmatrix.trans
#pragma unroll
        for (int ks = 0; ks < 4; ks++) {
            unsigned pa[2][4];
#pragma unroll
            for (int f = 0; f < 2; f++) {
                pa[f][0] = h2u(s[f][2*ks][0],   s[f][2*ks][1]);
                pa[f][1] = h2u(s[f][2*ks][2],   s[f][2*ks][3]);
                pa[f][2] = h2u(s[f][2*ks+1][0], s[f][2*ks+1][1]);
                pa[f][3] = h2u(s[f][2*ks+1][2], s[f][2*ks+1][3]);
            }
            unsigned voff = (unsigned)cur*KTB + ks*16*AP;
#pragma unroll
            for (int p = 0; p < 4; p++) {
                unsigned vb[4];
                ldsm4t(vb, aV[p] + voff);
                mma16(oacc[0][2*p],   pa[0], vb);
                mma16(oacc[1][2*p],   pa[1], vb);
                mma16(oacc[0][2*p+1], pa[0], vb + 2);
                mma16(oacc[1][2*p+1], pa[1], vb + 2);
            }
        }
    }

    // epilogue
    __half* Og = g_O + ((size_t)(b * S_ + qt * QT_)) * D_ + h * DH_;
#pragma unroll
    for (int f = 0; f < 2; f++) {
        float il = 1.0f / lrow[f][0], ih = 1.0f / lrow[f][1];
        int rl = r0 + f * 16 + g, rh = rl + 8;
#pragma unroll
        for (int dt = 0; dt < 8; dt++) {
            int c = dt * 8 + 2 * tg;
            *(unsigned*)&Og[(size_t)rl * D_ + c] = h2u(oacc[f][dt][0] * il, oacc[f][dt][1] * il);
            *(unsigned*)&Og[(size_t)rh * D_ + c] = h2u(oacc[f][dt][2] * ih, oacc[f][dt][3] * ih);
        }
    }
}

// ---------------------------------------------------------------------------
extern "C" void kernel_launch(void* const* d_in, const int* in_sizes, int n_in,
                              void* d_out, int out_size) {
    const float* x     = (const float*)d_in[0];
    const float* w_in  = (const float*)d_in[1];
    const float* b_in  = (const float*)d_in[2];
    const float* w_out = (const float*)d_in[3];
    const float* b_out = (const float*)d_in[4];
    float* out = (float*)d_out;

    const int gemm_smem = 6 * STG;                    // 110592 B
    const int attn_smem = 128*AP + 4*KTB;             // 55296 B
    cudaFuncSetAttribute(qkv_kernel,  cudaFuncAttributeMaxDynamicSharedMemorySize, gemm_smem);
    cudaFuncSetAttribute(out_kernel,  cudaFuncAttributeMaxDynamicSharedMemorySize, gemm_smem);
    cudaFuncSetAttribute(attn_kernel, cudaFuncAttributeMaxDynamicSharedMemorySize, attn_smem);

    __half* gx;  cudaGetSymbolAddress((void**)&gx,  g_X);
    __half* gwi; cudaGetSymbolAddress((void**)&gwi, g_Wi);
    __half* gwo; cudaGetSymbolAddress((void**)&gwo, g_Wo);
    int tot4 = XN4 + WIN4 + WON4;
    round_kernel<<<(tot4 + 255) / 256, 256>>>(
        (const float4*)x, (const float4*)w_in, (const float4*)w_out,
        (uint2*)gx, (uint2*)gwi, (uint2*)gwo);

    qkv_kernel<<<dim3(12, 128), 256, gemm_smem>>>(b_in);
    attn_kernel<<<dim3(S_ / QT_, H_, B_), 128, attn_smem>>>();
    out_kernel<<<dim3(4, 128), 256, gemm_smem>>>(b_out, out);
}